// round 15
// baseline (speedup 1.0000x reference)
#include <cuda_runtime.h>

// MaxPool2d k=2 s=2 valid, (32,64,224,224) fp32 -> (32,64,112,112).
// R14 = R12 body (the measured best: one thread = 2 output rows x 2 output
// cols, 4 front-batched lane-consecutive LDG.128 -> each warp load is one
// contiguous 512 B; 2 coalesced STG.64; plain cache ops) with BLOCK=128
// instead of 256 — the last unsampled dial. Finer CTA granularity (50176
// blocks) improves final-wave tail balance across 148 SMs and reduces
// per-quantum L1tex queue depth. Traffic unchanged: 411 MB read + 103 MB
// write, zero reuse, all accesses aligned.

#define NC_TOTAL   2048              // 32 * 64
#define IH         224
#define IW         224
#define OH         112
#define OW         112
#define IN_PLANE   (IH * IW)         // 50176
#define OUT_PLANE  (OH * OW)         // 12544
#define GROUPS_W   (IW / 4)          // 56 float4 columns (= 2 output cols each)
#define ROWPAIRS   (OH / 2)          // 56 output-row pairs
#define TOTAL_THREADS (NC_TOTAL * ROWPAIRS * GROUPS_W)   // 6,422,528
#define BLOCK      128

__global__ __launch_bounds__(BLOCK)
void maxpool2d_k2s2_coal128_kernel(const float* __restrict__ in, float* __restrict__ out) {
    int idx = blockIdx.x * BLOCK + threadIdx.x;
    if (idx >= TOTAL_THREADS) return;

    int g   = idx % GROUPS_W;            // float4 column (4 input cols -> 2 out cols)
    int t   = idx / GROUPS_W;
    int ohp = t % ROWPAIRS;              // which pair of output rows
    int nc  = t / ROWPAIRS;

    const int rstep = IW / 4;            // 56 float4 per input row
    const float4* base = reinterpret_cast<const float4*>(
        in + (size_t)nc * IN_PLANE + (size_t)(ohp * 4) * IW) + g;

    // 4 front-batched, independent, per-instruction fully coalesced LDG.128.
    float4 a = base[0 * rstep];          // input row 4*ohp
    float4 b = base[1 * rstep];          // input row 4*ohp+1
    float4 c = base[2 * rstep];          // input row 4*ohp+2
    float4 d = base[3 * rstep];          // input row 4*ohp+3

    float2 o0, o1;
    o0.x = fmaxf(fmaxf(a.x, a.y), fmaxf(b.x, b.y));
    o0.y = fmaxf(fmaxf(a.z, a.w), fmaxf(b.z, b.w));
    o1.x = fmaxf(fmaxf(c.x, c.y), fmaxf(d.x, d.y));
    o1.y = fmaxf(fmaxf(c.z, c.w), fmaxf(d.z, d.w));

    float2* orow0 = reinterpret_cast<float2*>(
        out + (size_t)nc * OUT_PLANE + (size_t)(ohp * 2) * OW) + g;
    float2* orow1 = orow0 + (OW / 2);    // next output row = 56 float2

    orow0[0] = o0;
    orow1[0] = o1;
}

extern "C" void kernel_launch(void* const* d_in, const int* in_sizes, int n_in,
                              void* d_out, int out_size) {
    const float* in = (const float*)d_in[0];
    float* out = (float*)d_out;
    int blocks = (TOTAL_THREADS + BLOCK - 1) / BLOCK;   // 50176
    maxpool2d_k2s2_coal128_kernel<<<blocks, BLOCK>>>(in, out);
}

// round 16
// speedup vs baseline: 1.0059x; 1.0059x over previous
#include <cuda_runtime.h>

// MaxPool2d k=2 s=2 valid, (32,64,224,224) fp32 -> (32,64,112,112).
// FINAL (R12, re-confirmed): HBM-roofline streaming kernel.
// One thread = 2 output rows x 2 output cols. 4 front-batched independent
// LDG.128 from input rows 4*ohp..4*ohp+3, all at the SAME float4 column
// index -> lane-consecutive addresses -> each warp load is one contiguous
// 512 B (4 fully-used 128B lines; L1 wavefronts halved vs strided layout).
// Outputs: two coalesced STG.64 (256 B contiguous per warp store).
// Plain cache ops. 411 MB read + 103 MB write of irreducible traffic at
// ~7.0 TB/s in-kernel (88.3% DRAM, 87.5% of HBM3e spec).
// Sampled and rejected on the timed metric: 8/16 loads per thread, 256-bit
// LDG/STG, streaming & evict-pinned L2 policies, persistent grid, forced
// occupancy (8 CTA/SM), block=128. This configuration measured best.

#define NC_TOTAL   2048              // 32 * 64
#define IH         224
#define IW         224
#define OH         112
#define OW         112
#define IN_PLANE   (IH * IW)         // 50176
#define OUT_PLANE  (OH * OW)         // 12544
#define GROUPS_W   (IW / 4)          // 56 float4 groups per input row (=2 out cols)
#define ROWPAIRS   (OH / 2)          // 56 output-row pairs
#define TOTAL_THREADS (NC_TOTAL * ROWPAIRS * GROUPS_W)   // 6,422,528

__global__ __launch_bounds__(256)
void maxpool2d_k2s2_coal_kernel(const float* __restrict__ in, float* __restrict__ out) {
    int idx = blockIdx.x * blockDim.x + threadIdx.x;
    if (idx >= TOTAL_THREADS) return;

    int g   = idx % GROUPS_W;            // float4 column index (4 input cols -> 2 out cols)
    int t   = idx / GROUPS_W;
    int ohp = t % ROWPAIRS;              // which pair of output rows
    int nc  = t / ROWPAIRS;

    const int rstep = IW / 4;            // 56 float4 per input row
    const float4* base = reinterpret_cast<const float4*>(
        in + (size_t)nc * IN_PLANE + (size_t)(ohp * 4) * IW) + g;

    // 4 front-batched, independent, per-instruction fully coalesced LDG.128.
    float4 a = base[0 * rstep];          // input row 4*ohp
    float4 b = base[1 * rstep];          // input row 4*ohp+1
    float4 c = base[2 * rstep];          // input row 4*ohp+2
    float4 d = base[3 * rstep];          // input row 4*ohp+3

    float2 o0, o1;
    o0.x = fmaxf(fmaxf(a.x, a.y), fmaxf(b.x, b.y));
    o0.y = fmaxf(fmaxf(a.z, a.w), fmaxf(b.z, b.w));
    o1.x = fmaxf(fmaxf(c.x, c.y), fmaxf(d.x, d.y));
    o1.y = fmaxf(fmaxf(c.z, c.w), fmaxf(d.z, d.w));

    float2* orow0 = reinterpret_cast<float2*>(
        out + (size_t)nc * OUT_PLANE + (size_t)(ohp * 2) * OW) + g;
    float2* orow1 = orow0 + (OW / 2);    // next output row = 56 float2

    orow0[0] = o0;
    orow1[0] = o1;
}

extern "C" void kernel_launch(void* const* d_in, const int* in_sizes, int n_in,
                              void* d_out, int out_size) {
    const float* in = (const float*)d_in[0];
    float* out = (float*)d_out;
    int blocks = (TOTAL_THREADS + 255) / 256;   // 25088
    maxpool2d_k2s2_coal_kernel<<<blocks, 256>>>(in, out);
}